// round 9
// baseline (speedup 1.0000x reference)
#include <cuda_runtime.h>
#include <cuda_bf16.h>
#include <cstdint>
#include <math.h>

#define LSEQ 32768
#define H 256
#define PP 128
#define CH 128
#define NCH 256
#define NL 4
#define GK 256

// ---------------- scratch (static __device__, no allocation) ----------------
__device__ float g_x[LSEQ * H];            // residual stream (fp32)
__device__ float g_bu[LSEQ * H];           // Bu, interleaved re/im (fp32)
__device__ float g_y[LSEQ * H];            // ssm output (fp32)
__device__ float g_p[LSEQ * 512];          // GLU pre-activations (fp32)
__device__ __nv_bfloat16 g_hh[LSEQ * H];   // ln/gelu output hi (also final x split hi)
__device__ __nv_bfloat16 g_hl[LSEQ * H];   // lo
__device__ __nv_bfloat16 g_sh[LSEQ * H];   // scan states hi
__device__ __nv_bfloat16 g_sl[LSEQ * H];   // scan states lo
__device__ float2 g_e[NCH * PP];
__device__ __nv_bfloat16 g_Wbh[NL * H * H], g_Wbl[NL * H * H];   // [N=2p][K=h]
__device__ __nv_bfloat16 g_Wch[NL * H * H], g_Wcl[NL * H * H];   // [N=h][K=2p]
__device__ __nv_bfloat16 g_Wgh[NL * 512 * H], g_Wgl[NL * 512 * H]; // [N=512][K=256]
__device__ float g_bg[NL * 512];
__device__ __nv_bfloat16 g_Woh[128 * H], g_Wol[128 * H];         // [N=128][K=256]
__device__ float g_boutP[128];
__device__ float2 g_abar[NL * PP];
__device__ float2 g_apow[NL * PP];
__device__ float g_x0[H];
__device__ __nv_bfloat16 g_h0h[H], g_h0l[H];

// ---------------- helpers ----------------
__device__ __forceinline__ uint32_t smem_u32(const void* p) {
    uint32_t a;
    asm("{ .reg .u64 t; cvta.to.shared.u64 t, %1; cvt.u32.u64 %0, t; }" : "=r"(a) : "l"(p));
    return a;
}
__device__ __forceinline__ void cpa(uint32_t s, const void* g) {
    asm volatile("cp.async.cg.shared.global [%0], [%1], 16;" :: "r"(s), "l"(g));
}
__device__ __forceinline__ void ldsm4(uint32_t* r, uint32_t a) {
    asm volatile("ldmatrix.sync.aligned.m8n8.x4.shared.b16 {%0,%1,%2,%3}, [%4];"
                 : "=r"(r[0]), "=r"(r[1]), "=r"(r[2]), "=r"(r[3]) : "r"(a));
}
__device__ __forceinline__ void mma16816(float* d, const uint32_t* a, uint32_t b0, uint32_t b1) {
    asm volatile("mma.sync.aligned.m16n8k16.row.col.f32.bf16.bf16.f32 "
                 "{%0,%1,%2,%3}, {%4,%5,%6,%7}, {%8,%9}, {%0,%1,%2,%3};"
                 : "+f"(d[0]), "+f"(d[1]), "+f"(d[2]), "+f"(d[3])
                 : "r"(a[0]), "r"(a[1]), "r"(a[2]), "r"(a[3]), "r"(b0), "r"(b1));
}
__device__ __forceinline__ void fsplit(float v, float& hi, float& lo) {
    hi = __bfloat162float(__float2bfloat16_rn(v));
    lo = v - hi;
}
__device__ __forceinline__ uint32_t pk(float a, float b) {
    __nv_bfloat162 t;
    t.x = __float2bfloat16_rn(a);
    t.y = __float2bfloat16_rn(b);
    return *(uint32_t*)&t;
}
__device__ __forceinline__ float2 upk(uint32_t u) {
    __nv_bfloat162 t = *(__nv_bfloat162*)&u;
    return make_float2(__bfloat162float(t.x), __bfloat162float(t.y));
}

// ---------------- bf16x3 tensor-core GEMM, BK=32, 2 CTAs/SM ----------------
// Stage: 4 buffers x (128 rows x 32 bf16 = 64B/row) = 32KB. 2 stages = 64KB/CTA.
#define SSTG 32768
#define O_AH 0
#define O_AL 8192
#define O_BH 16384
#define O_BL 24576
#define SM_GEMM (2 * SSTG)

// swizzled smem byte offset for (row, 16B-chunk ci) within one 8KB buffer
__device__ __forceinline__ uint32_t swz64(int r, int ci) {
    return (uint32_t)r * 64 + ((uint32_t)(ci ^ ((r >> 1) & 3)) << 4);
}

template <int EPI>
__global__ void __launch_bounds__(256, 2) tgemm(
    const __nv_bfloat16* __restrict__ Ah, const __nv_bfloat16* __restrict__ Al,
    const __nv_bfloat16* __restrict__ Bh, const __nv_bfloat16* __restrict__ Bl,
    const float* __restrict__ bias, float* __restrict__ C, int ldc, int ncols,
    const __nv_bfloat16* __restrict__ Uh, const __nv_bfloat16* __restrict__ Ul,
    const float* __restrict__ Dv) {
    extern __shared__ char smem[];
    uint32_t sb = smem_u32(smem);
    int tid = threadIdx.x, lane = tid & 31, wid = tid >> 5;
    int bm = blockIdx.y * 128, bn = blockIdx.x * 128;
    int Mw = (wid & 3) * 32, Nw = (wid >> 2) * 64;

    const int lr = tid >> 1;     // load row 0..127
    const int lc0 = tid & 1;     // chunks lc0, lc0+2

    auto ldst = [&](int buf, int kc) {
        uint32_t sd = sb + buf * SSTG;
        const __nv_bfloat16* pa  = Ah + (size_t)(bm + lr) * GK + kc;
        const __nv_bfloat16* pal = Al + (size_t)(bm + lr) * GK + kc;
        const __nv_bfloat16* pb  = Bh + (size_t)(bn + lr) * GK + kc;
        const __nv_bfloat16* pbl = Bl + (size_t)(bn + lr) * GK + kc;
#pragma unroll
        for (int cc = 0; cc < 2; cc++) {
            int ci = lc0 + cc * 2;
            uint32_t so = swz64(lr, ci);
            cpa(sd + O_AH + so, pa  + ci * 8);
            cpa(sd + O_AL + so, pal + ci * 8);
            cpa(sd + O_BH + so, pb  + ci * 8);
            cpa(sd + O_BL + so, pbl + ci * 8);
        }
        asm volatile("cp.async.commit_group;" ::: "memory");
    };

    float acc[2][8][4] = {};
    uint32_t a_h[2][4], a_l[2][4];
    int ra = (lane & 7) + ((lane >> 3) & 1) * 8;
    int cia = (lane >> 4) & 1;                 // A chunk parity within k16
    int rb = (lane & 7) + ((lane >> 4) & 1) * 8;
    int cib = (lane >> 3) & 1;                 // B chunk parity within k16

    ldst(0, 0);
    for (int c = 0; c < 8; c++) {
        if (c < 7) {
            ldst((c + 1) & 1, (c + 1) * 32);
            asm volatile("cp.async.wait_group 1;" ::: "memory");
        } else {
            asm volatile("cp.async.wait_group 0;" ::: "memory");
        }
        __syncthreads();
        uint32_t st = sb + (c & 1) * SSTG;
#pragma unroll
        for (int s = 0; s < 2; s++) {
#pragma unroll
            for (int mt = 0; mt < 2; mt++) {
                int r = Mw + mt * 16 + ra;
                uint32_t ad = st + swz64(r, s * 2 + cia);
                ldsm4(a_h[mt], ad + O_AH);
                ldsm4(a_l[mt], ad + O_AL);
            }
#pragma unroll
            for (int ng = 0; ng < 4; ng++) {
                uint32_t bh[4], bl[4];
                int r = Nw + ng * 16 + rb;
                uint32_t ad = st + swz64(r, s * 2 + cib);
                ldsm4(bh, ad + O_BH);
                ldsm4(bl, ad + O_BL);
#pragma unroll
                for (int mt = 0; mt < 2; mt++)
#pragma unroll
                    for (int h2 = 0; h2 < 2; h2++) {
                        int nf = ng * 2 + h2;
                        mma16816(acc[mt][nf], a_h[mt], bh[h2 * 2], bh[h2 * 2 + 1]);
                        mma16816(acc[mt][nf], a_l[mt], bh[h2 * 2], bh[h2 * 2 + 1]);
                        mma16816(acc[mt][nf], a_h[mt], bl[h2 * 2], bl[h2 * 2 + 1]);
                    }
            }
        }
        __syncthreads();
    }

#pragma unroll
    for (int mt = 0; mt < 2; mt++) {
        int r0 = bm + Mw + mt * 16 + (lane >> 2);
#pragma unroll
        for (int nf = 0; nf < 8; nf++) {
            int col = bn + Nw + nf * 8 + (lane & 3) * 2;
            float2 v0 = make_float2(acc[mt][nf][0], acc[mt][nf][1]);
            float2 v1 = make_float2(acc[mt][nf][2], acc[mt][nf][3]);
            if (EPI == 1) {
                float2 uh0 = upk(*(const uint32_t*)(Uh + (size_t)r0 * H + col));
                float2 ul0 = upk(*(const uint32_t*)(Ul + (size_t)r0 * H + col));
                float2 uh1 = upk(*(const uint32_t*)(Uh + (size_t)(r0 + 8) * H + col));
                float2 ul1 = upk(*(const uint32_t*)(Ul + (size_t)(r0 + 8) * H + col));
                float d0 = Dv[col], d1 = Dv[col + 1];
                v0.x += (uh0.x + ul0.x) * d0; v0.y += (uh0.y + ul0.y) * d1;
                v1.x += (uh1.x + ul1.x) * d0; v1.y += (uh1.y + ul1.y) * d1;
            }
            if (EPI >= 2) {
                float b0 = bias[col], b1 = bias[col + 1];
                v0.x += b0; v0.y += b1; v1.x += b0; v1.y += b1;
            }
            if (EPI != 3 || col < ncols) {
                *(float2*)(C + (size_t)r0 * ldc + col) = v0;
                *(float2*)(C + (size_t)(r0 + 8) * ldc + col) = v1;
            }
        }
    }
}

// ---------------- k_x0: latent expand + leaky_relu + layer-0 LN (one row) ----------------
__global__ void k_x0(const float* __restrict__ latent, const float* __restrict__ W,
                     const float* __restrict__ b,
                     const float* __restrict__ sc, const float* __restrict__ bi) {
    int j = threadIdx.x;
    float s = b[j];
    for (int i = 0; i < H; i++) s += latent[i] * W[i * H + j];
    s = s > 0.f ? s : 0.01f * s;
    g_x0[j] = s;
    float sum = s, sq = s * s;
#pragma unroll
    for (int off = 16; off; off >>= 1) {
        sum += __shfl_xor_sync(0xffffffffu, sum, off);
        sq  += __shfl_xor_sync(0xffffffffu, sq, off);
    }
    __shared__ float ws[8], wq[8], mu_s, r_s;
    int w = j >> 5, lane = j & 31;
    if (lane == 0) { ws[w] = sum; wq[w] = sq; }
    __syncthreads();
    if (j == 0) {
        float S = 0.f, Q = 0.f;
        for (int k = 0; k < 8; k++) { S += ws[k]; Q += wq[k]; }
        float mu = S * (1.f / H);
        mu_s = mu;
        r_s = rsqrtf(Q * (1.f / H) - mu * mu + 1e-6f);
    }
    __syncthreads();
    float t = (s - mu_s) * r_s * sc[j] + bi[j];
    float hi, lo;
    fsplit(t, hi, lo);
    g_h0h[j] = __float2bfloat16_rn(hi);
    g_h0l[j] = __float2bfloat16_rn(lo);
}

// ---------------- k_fill: broadcast x0 and ln(x0) split to all rows ----------------
__global__ void k_fill() {
    int idx = blockIdx.x * blockDim.x + threadIdx.x;  // L*64
    int c = idx & 63;
    ((float4*)g_x)[idx] = ((const float4*)g_x0)[c];
    ((uint2*)g_hh)[idx] = ((const uint2*)g_h0h)[c];
    ((uint2*)g_hl)[idx] = ((const uint2*)g_h0l)[c];
}

// ---------------- k_setup: merged weight preprocessing ----------------
__global__ void k_setup(const float* __restrict__ Lre, const float* __restrict__ Lim,
                        const float* __restrict__ Bre, const float* __restrict__ Bim,
                        const float* __restrict__ Cre, const float* __restrict__ Cim,
                        const float* __restrict__ lstep,
                        const float* __restrict__ W1, const float* __restrict__ b1,
                        const float* __restrict__ W2, const float* __restrict__ b2,
                        const float* __restrict__ Wout, const float* __restrict__ bout) {
    int bb = blockIdx.x;
    float hi, lo;
    if (bb < NL * PP) {
        int l = bb >> 7, p = bb & 127, h = threadIdx.x;
        float step = expf(lstep[l * PP + p]);
        float lr = Lre[l * PP + p], li = Lim[l * PP + p];
        float er = expf(lr * step);
        float sb, cb2;
        sincosf(li * step, &sb, &cb2);
        float abr = er * cb2, abi = er * sb;
        float den = lr * lr + li * li;
        float nr = abr - 1.f, ni = abi;
        float fr = (nr * lr + ni * li) / den;
        float fi = (ni * lr - nr * li) / den;
        float br = Bre[(l * PP + p) * H + h], bi = Bim[(l * PP + p) * H + h];
        float w0 = fr * br - fi * bi, w1 = fr * bi + fi * br;
        int ib0 = l * H * H + (2 * p) * H + h, ib1 = l * H * H + (2 * p + 1) * H + h;
        fsplit(w0, hi, lo); g_Wbh[ib0] = __float2bfloat16_rn(hi); g_Wbl[ib0] = __float2bfloat16_rn(lo);
        fsplit(w1, hi, lo); g_Wbh[ib1] = __float2bfloat16_rn(hi); g_Wbl[ib1] = __float2bfloat16_rn(lo);
        float c0 = 2.f * Cre[(l * H + h) * PP + p], c1 = -2.f * Cim[(l * H + h) * PP + p];
        int ic0 = l * H * H + h * H + 2 * p, ic1 = ic0 + 1;
        fsplit(c0, hi, lo); g_Wch[ic0] = __float2bfloat16_rn(hi); g_Wcl[ic0] = __float2bfloat16_rn(lo);
        fsplit(c1, hi, lo); g_Wch[ic1] = __float2bfloat16_rn(hi); g_Wcl[ic1] = __float2bfloat16_rn(lo);
        if (h == 0) {
            g_abar[l * PP + p] = make_float2(abr, abi);
            float er2 = expf(lr * step * (float)CH);
            float sb2, cb3;
            sincosf(li * step * (float)CH, &sb2, &cb3);
            g_apow[l * PP + p] = make_float2(er2 * cb3, er2 * sb2);
        }
    } else if (bb < NL * PP + 2048) {
        int idx = (bb - NL * PP) * 256 + threadIdx.x;  // NL*512*H
        int l = idx / (512 * H);
        int r = idx % (512 * H);
        int j = r / H, i = r % H;
        float w = (j < 256) ? W1[(l * H + i) * H + j] : W2[(l * H + i) * H + (j - 256)];
        fsplit(w, hi, lo);
        g_Wgh[idx] = __float2bfloat16_rn(hi);
        g_Wgl[idx] = __float2bfloat16_rn(lo);
        if (i == 0) g_bg[l * 512 + j] = (j < 256) ? b1[l * H + j] : b2[l * H + (j - 256)];
    } else {
        int idx = (bb - NL * PP - 2048) * 256 + threadIdx.x;  // 128*H
        int j = idx / H, i = idx % H;
        float w = (j < 64) ? Wout[i * 64 + j] : 0.f;
        fsplit(w, hi, lo);
        g_Woh[idx] = __float2bfloat16_rn(hi);
        g_Wol[idx] = __float2bfloat16_rn(lo);
        if (i == 0) g_boutP[j] = (j < 64) ? bout[j] : 0.f;
    }
}

// ---------------- layernorm + gelu (post-SSM), writes split bf16 ----------------
__global__ void k_lng(const float* __restrict__ x, __nv_bfloat16* __restrict__ oh,
                      __nv_bfloat16* __restrict__ ol,
                      const float* __restrict__ sc, const float* __restrict__ bi) {
    int row = blockIdx.x * 4 + (threadIdx.x >> 5);
    int lane = threadIdx.x & 31;
    const float* xr = x + (size_t)row * H;
    float4 a = *(const float4*)(xr + lane * 8);
    float4 b = *(const float4*)(xr + lane * 8 + 4);
    float v[8] = {a.x, a.y, a.z, a.w, b.x, b.y, b.z, b.w};
    float s = 0.f, q = 0.f;
#pragma unroll
    for (int i = 0; i < 8; i++) { s += v[i]; q += v[i] * v[i]; }
#pragma unroll
    for (int off = 16; off; off >>= 1) {
        s += __shfl_xor_sync(0xffffffffu, s, off);
        q += __shfl_xor_sync(0xffffffffu, q, off);
    }
    float mu = s * (1.f / H);
    float var = q * (1.f / H) - mu * mu;
    float r = rsqrtf(var + 1e-6f);
    float out[8];
#pragma unroll
    for (int i = 0; i < 8; i++) {
        int col = lane * 8 + i;
        float t = (v[i] - mu) * r * sc[col] + bi[col];
        float t3 = t * t * t;
        t = 0.5f * t * (1.f + tanhf(0.7978845608028654f * (t + 0.044715f * t3)));
        out[i] = t;
    }
    uint32_t* oh32 = (uint32_t*)oh;
    uint32_t* ol32 = (uint32_t*)ol;
#pragma unroll
    for (int q2 = 0; q2 < 4; q2++) {
        float h0, l0, h1, l1;
        fsplit(out[2 * q2], h0, l0);
        fsplit(out[2 * q2 + 1], h1, l1);
        oh32[(size_t)row * 128 + lane * 4 + q2] = pk(h0, h1);
        ol32[(size_t)row * 128 + lane * 4 + q2] = pk(l0, l1);
    }
}

// ---------------- chunked diagonal complex scan ----------------
__global__ void k_scan1(int l) {
    int c = blockIdx.x, p = threadIdx.x;
    float2 a = g_abar[l * PP + p];
    const float2* bu = (const float2*)g_bu + (size_t)c * CH * PP + p;
    float2 st = make_float2(0.f, 0.f);
#pragma unroll 8
    for (int t = 0; t < CH; t++) {
        float2 b = bu[(size_t)t * PP];
        st = make_float2(a.x * st.x - a.y * st.y + b.x, a.x * st.y + a.y * st.x + b.y);
    }
    g_e[c * PP + p] = st;
}

// carry prefix fused into the second pass: each CTA self-computes its carry-in.
__global__ void k_scan2c(int l, __nv_bfloat16* __restrict__ sh, __nv_bfloat16* __restrict__ sl) {
    int c = blockIdx.x, p = threadIdx.x;
    float2 a = g_abar[l * PP + p];
    float2 ap = g_apow[l * PP + p];
    float2 st = make_float2(0.f, 0.f);
#pragma unroll 4
    for (int j = 0; j < c; j++) {
        float2 e = g_e[j * PP + p];
        st = make_float2(ap.x * st.x - ap.y * st.y + e.x, ap.x * st.y + ap.y * st.x + e.y);
    }
    const float2* bu = (const float2*)g_bu + (size_t)c * CH * PP + p;
    uint32_t* sh32 = (uint32_t*)sh;
    uint32_t* sl32 = (uint32_t*)sl;
#pragma unroll 8
    for (int t = 0; t < CH; t++) {
        float2 b = bu[(size_t)t * PP];
        st = make_float2(a.x * st.x - a.y * st.y + b.x, a.x * st.y + a.y * st.x + b.y);
        float hr, lr2, hi2, li2;
        fsplit(st.x, hr, lr2);
        fsplit(st.y, hi2, li2);
        size_t row = (size_t)c * CH + t;
        sh32[row * 128 + p] = pk(hr, hi2);
        sl32[row * 128 + p] = pk(lr2, li2);
    }
}

// ---------------- GLU combine fused with next-layer prenorm (or raw split) ----------------
template <bool RAW>
__global__ void __launch_bounds__(256) k_gluln(const float* __restrict__ sc,
                                               const float* __restrict__ bi) {
    int tid = threadIdx.x;
    int rb = tid >> 6, t = tid & 63;          // 4 rows/block, 64 threads/row
    int row = blockIdx.x * 4 + rb;
    const float* prow = g_p + (size_t)row * 512;
    float4 a = *(const float4*)(prow + t * 4);
    float4 b = *(const float4*)(prow + 256 + t * 4);
    float4 x = ((float4*)g_x)[(size_t)row * 64 + t];
    x.x += a.x * (1.f / (1.f + expf(-b.x)));
    x.y += a.y * (1.f / (1.f + expf(-b.y)));
    x.z += a.z * (1.f / (1.f + expf(-b.z)));
    x.w += a.w * (1.f / (1.f + expf(-b.w)));
    ((float4*)g_x)[(size_t)row * 64 + t] = x;
    float v[4] = {x.x, x.y, x.z, x.w};
    float out[4];
    if (!RAW) {
        float s = v[0] + v[1] + v[2] + v[3];
        float q = v[0] * v[0] + v[1] * v[1] + v[2] * v[2] + v[3] * v[3];
#pragma unroll
        for (int off = 16; off; off >>= 1) {
            s += __shfl_xor_sync(0xffffffffu, s, off);
            q += __shfl_xor_sync(0xffffffffu, q, off);
        }
        __shared__ float ws[8], wq[8];
        int w = tid >> 5, lane = tid & 31;
        if (lane == 0) { ws[w] = s; wq[w] = q; }
        __syncthreads();
        float S = ws[rb * 2] + ws[rb * 2 + 1];
        float Q = wq[rb * 2] + wq[rb * 2 + 1];
        float mu = S * (1.f / H);
        float r = rsqrtf(Q * (1.f / H) - mu * mu + 1e-6f);
#pragma unroll
        for (int i = 0; i < 4; i++)
            out[i] = (v[i] - mu) * r * sc[t * 4 + i] + bi[t * 4 + i];
    } else {
#pragma unroll
        for (int i = 0; i < 4; i++) out[i] = v[i];
    }
    float h0, l0, h1, l1, h2, l2, h3, l3;
    fsplit(out[0], h0, l0); fsplit(out[1], h1, l1);
    fsplit(out[2], h2, l2); fsplit(out[3], h3, l3);
    ((uint2*)g_hh)[(size_t)row * 64 + t] = make_uint2(pk(h0, h1), pk(h2, h3));
    ((uint2*)g_hl)[(size_t)row * 64 + t] = make_uint2(pk(l0, l1), pk(l2, l3));
}

// ---------------- host launcher ----------------
extern "C" void kernel_launch(void* const* d_in, const int* in_sizes, int n_in,
                              void* d_out, int out_size) {
    const float* latent = (const float*)d_in[0];
    const float* Wexp   = (const float*)d_in[1];
    const float* bexp   = (const float*)d_in[2];
    const float* ns     = (const float*)d_in[3];
    const float* nb     = (const float*)d_in[4];
    const float* Lre    = (const float*)d_in[5];
    const float* Lim    = (const float*)d_in[6];
    const float* Bre    = (const float*)d_in[7];
    const float* Bim    = (const float*)d_in[8];
    const float* Cre    = (const float*)d_in[9];
    const float* Cim    = (const float*)d_in[10];
    const float* Dv     = (const float*)d_in[11];
    const float* lstep  = (const float*)d_in[12];
    const float* W1     = (const float*)d_in[13];
    const float* b1     = (const float*)d_in[14];
    const float* W2     = (const float*)d_in[15];
    const float* b2     = (const float*)d_in[16];
    const float* Wout   = (const float*)d_in[17];
    const float* bout   = (const float*)d_in[18];

    float *pbu, *py, *pp, *pbg, *pboutP;
    __nv_bfloat16 *phh, *phl, *psh, *psl, *pWbh, *pWbl, *pWch, *pWcl, *pWgh, *pWgl, *pWoh, *pWol;
    cudaGetSymbolAddress((void**)&pbu, g_bu);
    cudaGetSymbolAddress((void**)&py, g_y);
    cudaGetSymbolAddress((void**)&pp, g_p);
    cudaGetSymbolAddress((void**)&pbg, g_bg);
    cudaGetSymbolAddress((void**)&pboutP, g_boutP);
    cudaGetSymbolAddress((void**)&phh, g_hh);
    cudaGetSymbolAddress((void**)&phl, g_hl);
    cudaGetSymbolAddress((void**)&psh, g_sh);
    cudaGetSymbolAddress((void**)&psl, g_sl);
    cudaGetSymbolAddress((void**)&pWbh, g_Wbh);
    cudaGetSymbolAddress((void**)&pWbl, g_Wbl);
    cudaGetSymbolAddress((void**)&pWch, g_Wch);
    cudaGetSymbolAddress((void**)&pWcl, g_Wcl);
    cudaGetSymbolAddress((void**)&pWgh, g_Wgh);
    cudaGetSymbolAddress((void**)&pWgl, g_Wgl);
    cudaGetSymbolAddress((void**)&pWoh, g_Woh);
    cudaGetSymbolAddress((void**)&pWol, g_Wol);

    cudaFuncSetAttribute(tgemm<0>, cudaFuncAttributeMaxDynamicSharedMemorySize, SM_GEMM);
    cudaFuncSetAttribute(tgemm<1>, cudaFuncAttributeMaxDynamicSharedMemorySize, SM_GEMM);
    cudaFuncSetAttribute(tgemm<2>, cudaFuncAttributeMaxDynamicSharedMemorySize, SM_GEMM);
    cudaFuncSetAttribute(tgemm<3>, cudaFuncAttributeMaxDynamicSharedMemorySize, SM_GEMM);

    k_x0<<<1, 256>>>(latent, Wexp, bexp, ns, nb);
    k_fill<<<(LSEQ * 64) / 256, 256>>>();
    k_setup<<<NL * PP + 2048 + 128, 256>>>(Lre, Lim, Bre, Bim, Cre, Cim, lstep,
                                           W1, b1, W2, b2, Wout, bout);

    for (int l = 0; l < NL; l++) {
        tgemm<0><<<dim3(2, 256), 256, SM_GEMM>>>(phh, phl, pWbh + l * H * H, pWbl + l * H * H,
                                                 nullptr, pbu, H, H, nullptr, nullptr, nullptr);
        k_scan1<<<NCH, PP>>>(l);
        k_scan2c<<<NCH, PP>>>(l, psh, psl);
        tgemm<1><<<dim3(2, 256), 256, SM_GEMM>>>(psh, psl, pWch + l * H * H, pWcl + l * H * H,
                                                 nullptr, py, H, H, phh, phl, Dv + l * H);
        k_lng<<<LSEQ / 4, 128>>>(py, phh, phl, ns + l * H, nb + l * H);
        tgemm<2><<<dim3(4, 256), 256, SM_GEMM>>>(phh, phl, pWgh + l * 512 * H, pWgl + l * 512 * H,
                                                 pbg + l * 512, pp, 512, 512, nullptr, nullptr, nullptr);
        if (l < NL - 1)
            k_gluln<false><<<LSEQ / 4, 256>>>(ns + (l + 1) * H, nb + (l + 1) * H);
        else
            k_gluln<true><<<LSEQ / 4, 256>>>(nullptr, nullptr);
    }
    tgemm<3><<<dim3(1, 256), 256, SM_GEMM>>>(phh, phl, pWoh, pWol, pboutP, (float*)d_out,
                                             64, 64, nullptr, nullptr, nullptr);
}

// round 12
// speedup vs baseline: 1.1332x; 1.1332x over previous
#include <cuda_runtime.h>
#include <cuda_bf16.h>
#include <cstdint>
#include <math.h>

#define LSEQ 32768
#define H 256
#define PP 128
#define CH 128
#define NCH 256
#define NL 4
#define GK 256

// ---------------- scratch (static __device__, no allocation) ----------------
__device__ float g_x[LSEQ * H];            // residual stream (fp32)
__device__ float g_bu[LSEQ * H];           // Bu, interleaved re/im (fp32)
__device__ float g_y[LSEQ * H];            // ssm output (fp32)
__device__ float g_p[LSEQ * 512];          // GLU pre-activations (fp32)
__device__ __nv_bfloat16 g_hh[LSEQ * H];   // ln/gelu output hi (also final x split hi)
__device__ __nv_bfloat16 g_hl[LSEQ * H];   // lo
__device__ __nv_bfloat16 g_sh[LSEQ * H];   // scan states hi
__device__ __nv_bfloat16 g_sl[LSEQ * H];   // scan states lo
__device__ float2 g_e[NCH * PP];
__device__ __nv_bfloat16 g_Wbh[NL * H * H], g_Wbl[NL * H * H];   // [N=2p][K=h]
__device__ __nv_bfloat16 g_Wch[NL * H * H], g_Wcl[NL * H * H];   // [N=h][K=2p]
__device__ __nv_bfloat16 g_Wgh[NL * 512 * H], g_Wgl[NL * 512 * H]; // [N=512][K=256]
__device__ float g_bg[NL * 512];
__device__ __nv_bfloat16 g_Woh[128 * H], g_Wol[128 * H];         // [N=128][K=256]
__device__ float g_boutP[128];
__device__ float2 g_abar[NL * PP];
__device__ float2 g_apow[NL * PP];
__device__ float g_x0[H];
__device__ __nv_bfloat16 g_h0h[H], g_h0l[H];

// ---------------- helpers ----------------
__device__ __forceinline__ uint32_t smem_u32(const void* p) {
    uint32_t a;
    asm("{ .reg .u64 t; cvta.to.shared.u64 t, %1; cvt.u32.u64 %0, t; }" : "=r"(a) : "l"(p));
    return a;
}
__device__ __forceinline__ void cpa(uint32_t s, const void* g) {
    asm volatile("cp.async.cg.shared.global [%0], [%1], 16;" :: "r"(s), "l"(g));
}
__device__ __forceinline__ void ldsm4(uint32_t* r, uint32_t a) {
    asm volatile("ldmatrix.sync.aligned.m8n8.x4.shared.b16 {%0,%1,%2,%3}, [%4];"
                 : "=r"(r[0]), "=r"(r[1]), "=r"(r[2]), "=r"(r[3]) : "r"(a));
}
__device__ __forceinline__ void mma16816(float* d, const uint32_t* a, uint32_t b0, uint32_t b1) {
    asm volatile("mma.sync.aligned.m16n8k16.row.col.f32.bf16.bf16.f32 "
                 "{%0,%1,%2,%3}, {%4,%5,%6,%7}, {%8,%9}, {%0,%1,%2,%3};"
                 : "+f"(d[0]), "+f"(d[1]), "+f"(d[2]), "+f"(d[3])
                 : "r"(a[0]), "r"(a[1]), "r"(a[2]), "r"(a[3]), "r"(b0), "r"(b1));
}
__device__ __forceinline__ void fsplit(float v, float& hi, float& lo) {
    hi = __bfloat162float(__float2bfloat16_rn(v));
    lo = v - hi;
}
__device__ __forceinline__ uint32_t pk(float a, float b) {
    __nv_bfloat162 t;
    t.x = __float2bfloat16_rn(a);
    t.y = __float2bfloat16_rn(b);
    return *(uint32_t*)&t;
}
__device__ __forceinline__ float2 upk(uint32_t u) {
    __nv_bfloat162 t = *(__nv_bfloat162*)&u;
    return make_float2(__bfloat162float(t.x), __bfloat162float(t.y));
}

// ---------------- bf16x3 tensor-core GEMM, BM=128 BN=64 BK=64, 2 CTAs/SM ----------------
// Stage: A hi/lo 2x16KB + B hi/lo 2x8KB = 48KB. 2 stages = 96KB/CTA -> 2 CTAs/SM.
#define SSTG 49152
#define O_AH 0
#define O_AL 16384
#define O_BH 32768
#define O_BL 40960
#define SM_GEMM (2 * SSTG)

template <int EPI>
__global__ void __launch_bounds__(256, 2) tgemm(
    const __nv_bfloat16* __restrict__ Ah, const __nv_bfloat16* __restrict__ Al,
    const __nv_bfloat16* __restrict__ Bh, const __nv_bfloat16* __restrict__ Bl,
    const float* __restrict__ bias, float* __restrict__ C, int ldc, int ncols,
    const __nv_bfloat16* __restrict__ Uh, const __nv_bfloat16* __restrict__ Ul,
    const float* __restrict__ Dv) {
    extern __shared__ char smem[];
    uint32_t sb = smem_u32(smem);
    int tid = threadIdx.x, lane = tid & 31, wid = tid >> 5;
    int bm = blockIdx.y * 128, bn = blockIdx.x * 64;
    int Mw = (wid & 3) * 32, Nw = (wid >> 2) * 32;

    auto ldst = [&](int buf, int kc) {
        uint32_t sd = sb + buf * SSTG;
        // A: 128 rows x 8 chunks of 16B (hi+lo)
#pragma unroll
        for (int i = 0; i < 4; i++) {
            int id = tid + i * 256;
            int row = id >> 3, ci = id & 7;
            uint32_t so = (uint32_t)row * 128 + (uint32_t)((ci ^ (row & 7)) << 4);
            const __nv_bfloat16* pa = Ah + (size_t)(bm + row) * GK + kc + ci * 8;
            const __nv_bfloat16* pl = Al + (size_t)(bm + row) * GK + kc + ci * 8;
            cpa(sd + O_AH + so, pa);
            cpa(sd + O_AL + so, pl);
        }
        // B: 64 rows x 8 chunks of 16B (hi+lo)
#pragma unroll
        for (int i = 0; i < 2; i++) {
            int id = tid + i * 256;
            int row = id >> 3, ci = id & 7;
            uint32_t so = (uint32_t)row * 128 + (uint32_t)((ci ^ (row & 7)) << 4);
            const __nv_bfloat16* pb = Bh + (size_t)(bn + row) * GK + kc + ci * 8;
            const __nv_bfloat16* pl = Bl + (size_t)(bn + row) * GK + kc + ci * 8;
            cpa(sd + O_BH + so, pb);
            cpa(sd + O_BL + so, pl);
        }
        asm volatile("cp.async.commit_group;" ::: "memory");
    };

    float acc[2][4][4] = {};
    uint32_t a_h[2][4], a_l[2][4];
    int ra = (lane & 7) + ((lane >> 3) & 1) * 8;
    int ca = (lane >> 4) << 4;                 // 0 or 16 bytes within k16 pair
    int rb = (lane & 7) + ((lane >> 4) & 1) * 8;
    int cb = ((lane >> 3) & 1) << 4;

    ldst(0, 0);
    for (int c = 0; c < 4; c++) {
        if (c < 3) {
            ldst((c + 1) & 1, (c + 1) * 64);
            asm volatile("cp.async.wait_group 1;" ::: "memory");
        } else {
            asm volatile("cp.async.wait_group 0;" ::: "memory");
        }
        __syncthreads();
        uint32_t st = sb + (c & 1) * SSTG;
#pragma unroll
        for (int s = 0; s < 4; s++) {
#pragma unroll
            for (int mt = 0; mt < 2; mt++) {
                int r = Mw + mt * 16 + ra;
                uint32_t ad = st + (uint32_t)r * 128 + (((uint32_t)(s * 32 + ca)) ^ ((uint32_t)(r & 7) << 4));
                ldsm4(a_h[mt], ad + O_AH);
                ldsm4(a_l[mt], ad + O_AL);
            }
#pragma unroll
            for (int ng = 0; ng < 2; ng++) {
                uint32_t bh[4], bl[4];
                int r = Nw + ng * 16 + rb;
                uint32_t ad = st + (uint32_t)r * 128 + (((uint32_t)(s * 32 + cb)) ^ ((uint32_t)(r & 7) << 4));
                ldsm4(bh, ad + O_BH);
                ldsm4(bl, ad + O_BL);
#pragma unroll
                for (int mt = 0; mt < 2; mt++)
#pragma unroll
                    for (int h2 = 0; h2 < 2; h2++) {
                        int nf = ng * 2 + h2;
                        mma16816(acc[mt][nf], a_h[mt], bh[h2 * 2], bh[h2 * 2 + 1]);
                        mma16816(acc[mt][nf], a_l[mt], bh[h2 * 2], bh[h2 * 2 + 1]);
                        mma16816(acc[mt][nf], a_h[mt], bl[h2 * 2], bl[h2 * 2 + 1]);
                    }
            }
        }
        __syncthreads();
    }

#pragma unroll
    for (int mt = 0; mt < 2; mt++) {
        int r0 = bm + Mw + mt * 16 + (lane >> 2);
#pragma unroll
        for (int nf = 0; nf < 4; nf++) {
            int col = bn + Nw + nf * 8 + (lane & 3) * 2;
            float2 v0 = make_float2(acc[mt][nf][0], acc[mt][nf][1]);
            float2 v1 = make_float2(acc[mt][nf][2], acc[mt][nf][3]);
            if (EPI == 1) {
                float2 uh0 = upk(*(const uint32_t*)(Uh + (size_t)r0 * H + col));
                float2 ul0 = upk(*(const uint32_t*)(Ul + (size_t)r0 * H + col));
                float2 uh1 = upk(*(const uint32_t*)(Uh + (size_t)(r0 + 8) * H + col));
                float2 ul1 = upk(*(const uint32_t*)(Ul + (size_t)(r0 + 8) * H + col));
                float d0 = Dv[col], d1 = Dv[col + 1];
                v0.x += (uh0.x + ul0.x) * d0; v0.y += (uh0.y + ul0.y) * d1;
                v1.x += (uh1.x + ul1.x) * d0; v1.y += (uh1.y + ul1.y) * d1;
            }
            if (EPI >= 2) {
                float b0 = bias[col], b1 = bias[col + 1];
                v0.x += b0; v0.y += b1; v1.x += b0; v1.y += b1;
            }
            *(float2*)(C + (size_t)r0 * ldc + col) = v0;
            *(float2*)(C + (size_t)(r0 + 8) * ldc + col) = v1;
        }
    }
}

// ---------------- k_x0: latent expand + leaky_relu + layer-0 LN (one row) ----------------
__global__ void k_x0(const float* __restrict__ latent, const float* __restrict__ W,
                     const float* __restrict__ b,
                     const float* __restrict__ sc, const float* __restrict__ bi) {
    int j = threadIdx.x;
    float s = b[j];
    for (int i = 0; i < H; i++) s += latent[i] * W[i * H + j];
    s = s > 0.f ? s : 0.01f * s;
    g_x0[j] = s;
    float sum = s, sq = s * s;
#pragma unroll
    for (int off = 16; off; off >>= 1) {
        sum += __shfl_xor_sync(0xffffffffu, sum, off);
        sq  += __shfl_xor_sync(0xffffffffu, sq, off);
    }
    __shared__ float ws[8], wq[8], mu_s, r_s;
    int w = j >> 5, lane = j & 31;
    if (lane == 0) { ws[w] = sum; wq[w] = sq; }
    __syncthreads();
    if (j == 0) {
        float S = 0.f, Q = 0.f;
        for (int k = 0; k < 8; k++) { S += ws[k]; Q += wq[k]; }
        float mu = S * (1.f / H);
        mu_s = mu;
        r_s = rsqrtf(Q * (1.f / H) - mu * mu + 1e-6f);
    }
    __syncthreads();
    float t = (s - mu_s) * r_s * sc[j] + bi[j];
    float hi, lo;
    fsplit(t, hi, lo);
    g_h0h[j] = __float2bfloat16_rn(hi);
    g_h0l[j] = __float2bfloat16_rn(lo);
}

// ---------------- k_fill: broadcast x0 and ln(x0) split to all rows ----------------
__global__ void k_fill() {
    int idx = blockIdx.x * blockDim.x + threadIdx.x;  // L*64
    int c = idx & 63;
    ((float4*)g_x)[idx] = ((const float4*)g_x0)[c];
    ((uint2*)g_hh)[idx] = ((const uint2*)g_h0h)[c];
    ((uint2*)g_hl)[idx] = ((const uint2*)g_h0l)[c];
}

// ---------------- k_setup: merged weight preprocessing ----------------
__global__ void k_setup(const float* __restrict__ Lre, const float* __restrict__ Lim,
                        const float* __restrict__ Bre, const float* __restrict__ Bim,
                        const float* __restrict__ Cre, const float* __restrict__ Cim,
                        const float* __restrict__ lstep,
                        const float* __restrict__ W1, const float* __restrict__ b1,
                        const float* __restrict__ W2, const float* __restrict__ b2,
                        const float* __restrict__ Wout, const float* __restrict__ bout) {
    int bb = blockIdx.x;
    float hi, lo;
    if (bb < NL * PP) {
        int l = bb >> 7, p = bb & 127, h = threadIdx.x;
        float step = expf(lstep[l * PP + p]);
        float lr = Lre[l * PP + p], li = Lim[l * PP + p];
        float er = expf(lr * step);
        float sb, cb2;
        sincosf(li * step, &sb, &cb2);
        float abr = er * cb2, abi = er * sb;
        float den = lr * lr + li * li;
        float nr = abr - 1.f, ni = abi;
        float fr = (nr * lr + ni * li) / den;
        float fi = (ni * lr - nr * li) / den;
        float br = Bre[(l * PP + p) * H + h], bi = Bim[(l * PP + p) * H + h];
        float w0 = fr * br - fi * bi, w1 = fr * bi + fi * br;
        int ib0 = l * H * H + (2 * p) * H + h, ib1 = l * H * H + (2 * p + 1) * H + h;
        fsplit(w0, hi, lo); g_Wbh[ib0] = __float2bfloat16_rn(hi); g_Wbl[ib0] = __float2bfloat16_rn(lo);
        fsplit(w1, hi, lo); g_Wbh[ib1] = __float2bfloat16_rn(hi); g_Wbl[ib1] = __float2bfloat16_rn(lo);
        float c0 = 2.f * Cre[(l * H + h) * PP + p], c1 = -2.f * Cim[(l * H + h) * PP + p];
        int ic0 = l * H * H + h * H + 2 * p, ic1 = ic0 + 1;
        fsplit(c0, hi, lo); g_Wch[ic0] = __float2bfloat16_rn(hi); g_Wcl[ic0] = __float2bfloat16_rn(lo);
        fsplit(c1, hi, lo); g_Wch[ic1] = __float2bfloat16_rn(hi); g_Wcl[ic1] = __float2bfloat16_rn(lo);
        if (h == 0) {
            g_abar[l * PP + p] = make_float2(abr, abi);
            float er2 = expf(lr * step * (float)CH);
            float sb2, cb3;
            sincosf(li * step * (float)CH, &sb2, &cb3);
            g_apow[l * PP + p] = make_float2(er2 * cb3, er2 * sb2);
        }
    } else if (bb < NL * PP + 2048) {
        int idx = (bb - NL * PP) * 256 + threadIdx.x;  // NL*512*H
        int l = idx / (512 * H);
        int r = idx % (512 * H);
        int j = r / H, i = r % H;
        float w = (j < 256) ? W1[(l * H + i) * H + j] : W2[(l * H + i) * H + (j - 256)];
        fsplit(w, hi, lo);
        g_Wgh[idx] = __float2bfloat16_rn(hi);
        g_Wgl[idx] = __float2bfloat16_rn(lo);
        if (i == 0) g_bg[l * 512 + j] = (j < 256) ? b1[l * H + j] : b2[l * H + (j - 256)];
    } else {
        int idx = (bb - NL * PP - 2048) * 256 + threadIdx.x;  // 128*H
        int j = idx / H, i = idx % H;
        float w = (j < 64) ? Wout[i * 64 + j] : 0.f;
        fsplit(w, hi, lo);
        g_Woh[idx] = __float2bfloat16_rn(hi);
        g_Wol[idx] = __float2bfloat16_rn(lo);
        if (i == 0) g_boutP[j] = (j < 64) ? bout[j] : 0.f;
    }
}

// ---------------- layernorm + gelu (post-SSM), writes split bf16 ----------------
__global__ void k_lng(const float* __restrict__ x, __nv_bfloat16* __restrict__ oh,
                      __nv_bfloat16* __restrict__ ol,
                      const float* __restrict__ sc, const float* __restrict__ bi) {
    int row = blockIdx.x * 4 + (threadIdx.x >> 5);
    int lane = threadIdx.x & 31;
    const float* xr = x + (size_t)row * H;
    float4 a = *(const float4*)(xr + lane * 8);
    float4 b = *(const float4*)(xr + lane * 8 + 4);
    float v[8] = {a.x, a.y, a.z, a.w, b.x, b.y, b.z, b.w};
    float s = 0.f, q = 0.f;
#pragma unroll
    for (int i = 0; i < 8; i++) { s += v[i]; q += v[i] * v[i]; }
#pragma unroll
    for (int off = 16; off; off >>= 1) {
        s += __shfl_xor_sync(0xffffffffu, s, off);
        q += __shfl_xor_sync(0xffffffffu, q, off);
    }
    float mu = s * (1.f / H);
    float var = q * (1.f / H) - mu * mu;
    float r = rsqrtf(var + 1e-6f);
    float out[8];
#pragma unroll
    for (int i = 0; i < 8; i++) {
        int col = lane * 8 + i;
        float t = (v[i] - mu) * r * sc[col] + bi[col];
        float t3 = t * t * t;
        t = 0.5f * t * (1.f + tanhf(0.7978845608028654f * (t + 0.044715f * t3)));
        out[i] = t;
    }
    uint32_t* oh32 = (uint32_t*)oh;
    uint32_t* ol32 = (uint32_t*)ol;
#pragma unroll
    for (int q2 = 0; q2 < 4; q2++) {
        float h0, l0, h1, l1;
        fsplit(out[2 * q2], h0, l0);
        fsplit(out[2 * q2 + 1], h1, l1);
        oh32[(size_t)row * 128 + lane * 4 + q2] = pk(h0, h1);
        ol32[(size_t)row * 128 + lane * 4 + q2] = pk(l0, l1);
    }
}

// ---------------- chunked diagonal complex scan ----------------
__global__ void k_scan1(int l) {
    int c = blockIdx.x, p = threadIdx.x;
    float2 a = g_abar[l * PP + p];
    const float2* bu = (const float2*)g_bu + (size_t)c * CH * PP + p;
    float2 st = make_float2(0.f, 0.f);
#pragma unroll 8
    for (int t = 0; t < CH; t++) {
        float2 b = bu[(size_t)t * PP];
        st = make_float2(a.x * st.x - a.y * st.y + b.x, a.x * st.y + a.y * st.x + b.y);
    }
    g_e[c * PP + p] = st;
}

// carry prefix fused into the second pass: each CTA self-computes its carry-in.
__global__ void k_scan2c(int l, __nv_bfloat16* __restrict__ sh, __nv_bfloat16* __restrict__ sl) {
    int c = blockIdx.x, p = threadIdx.x;
    float2 a = g_abar[l * PP + p];
    float2 ap = g_apow[l * PP + p];
    float2 st = make_float2(0.f, 0.f);
#pragma unroll 4
    for (int j = 0; j < c; j++) {
        float2 e = g_e[j * PP + p];
        st = make_float2(ap.x * st.x - ap.y * st.y + e.x, ap.x * st.y + ap.y * st.x + e.y);
    }
    const float2* bu = (const float2*)g_bu + (size_t)c * CH * PP + p;
    uint32_t* sh32 = (uint32_t*)sh;
    uint32_t* sl32 = (uint32_t*)sl;
#pragma unroll 8
    for (int t = 0; t < CH; t++) {
        float2 b = bu[(size_t)t * PP];
        st = make_float2(a.x * st.x - a.y * st.y + b.x, a.x * st.y + a.y * st.x + b.y);
        float hr, lr2, hi2, li2;
        fsplit(st.x, hr, lr2);
        fsplit(st.y, hi2, li2);
        size_t row = (size_t)c * CH + t;
        sh32[row * 128 + p] = pk(hr, hi2);
        sl32[row * 128 + p] = pk(lr2, li2);
    }
}

// ---------------- GLU combine fused with next-layer prenorm (or raw split) ----------------
template <bool RAW>
__global__ void __launch_bounds__(256) k_gluln(const float* __restrict__ sc,
                                               const float* __restrict__ bi) {
    int tid = threadIdx.x;
    int rb = tid >> 6, t = tid & 63;          // 4 rows/block, 64 threads/row
    int row = blockIdx.x * 4 + rb;
    const float* prow = g_p + (size_t)row * 512;
    float4 a = *(const float4*)(prow + t * 4);
    float4 b = *(const float4*)(prow + 256 + t * 4);
    float4 x = ((float4*)g_x)[(size_t)row * 64 + t];
    x.x += a.x * (1.f / (1.f + expf(-b.x)));
    x.y += a.y * (1.f / (1.f + expf(-b.y)));
    x.z += a.z * (1.f / (1.f + expf(-b.z)));
    x.w += a.w * (1.f / (1.f + expf(-b.w)));
    ((float4*)g_x)[(size_t)row * 64 + t] = x;
    float v[4] = {x.x, x.y, x.z, x.w};
    float out[4];
    if (!RAW) {
        float s = v[0] + v[1] + v[2] + v[3];
        float q = v[0] * v[0] + v[1] * v[1] + v[2] * v[2] + v[3] * v[3];
#pragma unroll
        for (int off = 16; off; off >>= 1) {
            s += __shfl_xor_sync(0xffffffffu, s, off);
            q += __shfl_xor_sync(0xffffffffu, q, off);
        }
        __shared__ float ws[8], wq[8];
        int w = tid >> 5, lane = tid & 31;
        if (lane == 0) { ws[w] = s; wq[w] = q; }
        __syncthreads();
        float S = ws[rb * 2] + ws[rb * 2 + 1];
        float Q = wq[rb * 2] + wq[rb * 2 + 1];
        float mu = S * (1.f / H);
        float r = rsqrtf(Q * (1.f / H) - mu * mu + 1e-6f);
#pragma unroll
        for (int i = 0; i < 4; i++)
            out[i] = (v[i] - mu) * r * sc[t * 4 + i] + bi[t * 4 + i];
    } else {
#pragma unroll
        for (int i = 0; i < 4; i++) out[i] = v[i];
    }
    float h0, l0, h1, l1, h2, l2, h3, l3;
    fsplit(out[0], h0, l0); fsplit(out[1], h1, l1);
    fsplit(out[2], h2, l2); fsplit(out[3], h3, l3);
    ((uint2*)g_hh)[(size_t)row * 64 + t] = make_uint2(pk(h0, h1), pk(h2, h3));
    ((uint2*)g_hl)[(size_t)row * 64 + t] = make_uint2(pk(l0, l1), pk(l2, l3));
}

// ---------------- host launcher ----------------
extern "C" void kernel_launch(void* const* d_in, const int* in_sizes, int n_in,
                              void* d_out, int out_size) {
    const float* latent = (const float*)d_in[0];
    const float* Wexp   = (const float*)d_in[1];
    const float* bexp   = (const float*)d_in[2];
    const float* ns     = (const float*)d_in[3];
    const float* nb     = (const float*)d_in[4];
    const float* Lre    = (const float*)d_in[5];
    const float* Lim    = (const float*)d_in[6];
    const float* Bre    = (const float*)d_in[7];
    const float* Bim    = (const float*)d_in[8];
    const float* Cre    = (const float*)d_in[9];
    const float* Cim    = (const float*)d_in[10];
    const float* Dv     = (const float*)d_in[11];
    const float* lstep  = (const float*)d_in[12];
    const float* W1     = (const float*)d_in[13];
    const float* b1     = (const float*)d_in[14];
    const float* W2     = (const float*)d_in[15];
    const float* b2     = (const float*)d_in[16];
    const float* Wout   = (const float*)d_in[17];
    const float* bout   = (const float*)d_in[18];

    float *pbu, *py, *pp, *pbg, *pboutP;
    __nv_bfloat16 *phh, *phl, *psh, *psl, *pWbh, *pWbl, *pWch, *pWcl, *pWgh, *pWgl, *pWoh, *pWol;
    cudaGetSymbolAddress((void**)&pbu, g_bu);
    cudaGetSymbolAddress((void**)&py, g_y);
    cudaGetSymbolAddress((void**)&pp, g_p);
    cudaGetSymbolAddress((void**)&pbg, g_bg);
    cudaGetSymbolAddress((void**)&pboutP, g_boutP);
    cudaGetSymbolAddress((void**)&phh, g_hh);
    cudaGetSymbolAddress((void**)&phl, g_hl);
    cudaGetSymbolAddress((void**)&psh, g_sh);
    cudaGetSymbolAddress((void**)&psl, g_sl);
    cudaGetSymbolAddress((void**)&pWbh, g_Wbh);
    cudaGetSymbolAddress((void**)&pWbl, g_Wbl);
    cudaGetSymbolAddress((void**)&pWch, g_Wch);
    cudaGetSymbolAddress((void**)&pWcl, g_Wcl);
    cudaGetSymbolAddress((void**)&pWgh, g_Wgh);
    cudaGetSymbolAddress((void**)&pWgl, g_Wgl);
    cudaGetSymbolAddress((void**)&pWoh, g_Woh);
    cudaGetSymbolAddress((void**)&pWol, g_Wol);

    cudaFuncSetAttribute(tgemm<0>, cudaFuncAttributeMaxDynamicSharedMemorySize, SM_GEMM);
    cudaFuncSetAttribute(tgemm<1>, cudaFuncAttributeMaxDynamicSharedMemorySize, SM_GEMM);
    cudaFuncSetAttribute(tgemm<2>, cudaFuncAttributeMaxDynamicSharedMemorySize, SM_GEMM);

    k_x0<<<1, 256>>>(latent, Wexp, bexp, ns, nb);
    k_fill<<<(LSEQ * 64) / 256, 256>>>();
    k_setup<<<NL * PP + 2048 + 128, 256>>>(Lre, Lim, Bre, Bim, Cre, Cim, lstep,
                                           W1, b1, W2, b2, Wout, bout);

    for (int l = 0; l < NL; l++) {
        tgemm<0><<<dim3(4, 256), 256, SM_GEMM>>>(phh, phl, pWbh + l * H * H, pWbl + l * H * H,
                                                 nullptr, pbu, H, H, nullptr, nullptr, nullptr);
        k_scan1<<<NCH, PP>>>(l);
        k_scan2c<<<NCH, PP>>>(l, psh, psl);
        tgemm<1><<<dim3(4, 256), 256, SM_GEMM>>>(psh, psl, pWch + l * H * H, pWcl + l * H * H,
                                                 nullptr, py, H, H, phh, phl, Dv + l * H);
        k_lng<<<LSEQ / 4, 128>>>(py, phh, phl, ns + l * H, nb + l * H);
        tgemm<2><<<dim3(8, 256), 256, SM_GEMM>>>(phh, phl, pWgh + l * 512 * H, pWgl + l * 512 * H,
                                                 pbg + l * 512, pp, 512, 512, nullptr, nullptr, nullptr);
        if (l < NL - 1)
            k_gluln<false><<<LSEQ / 4, 256>>>(ns + (l + 1) * H, nb + (l + 1) * H);
        else
            k_gluln<true><<<LSEQ / 4, 256>>>(nullptr, nullptr);
    }
    tgemm<2><<<dim3(1, 256), 256, SM_GEMM>>>(phh, phl, pWoh, pWol, pboutP, (float*)d_out,
                                             64, 64, nullptr, nullptr, nullptr);
}